// round 16
// baseline (speedup 1.0000x reference)
#include <cuda_runtime.h>

// Problem constants (fixed by reference setup_inputs)
#define NB   2
#define TT   2048
#define CC   1024
#define NH   16
#define HD   64
#define WIN  512
#define MTOT (NB * TT)          // 4096
#define NQKV (3 * CC)           // 3072

// Scratch (no allocation allowed) — 64 MB total
__device__ __align__(16) float g_Q[NB * NH * TT * HD];
__device__ __align__(16) float g_K[NB * NH * TT * HD];
__device__ __align__(16) float g_V[NB * NH * TT * HD];
__device__ __align__(16) float g_Y[MTOT * CC];

// ---------------------------------------------------------------------------
// Tiled fp32 GEMM: 128x64 block tile, BK=16, 256 threads, 8x4 per thread.
// MODE 0: C = x @ w_attn, epilogue scatters into Q/K/V as [B,H,T,D],
//         folding the 1/sqrt(D) scale into Q.
// MODE 1: C = g_Y @ w_proj, plain store to output.
// ---------------------------------------------------------------------------
template <int MODE>
__global__ __launch_bounds__(256)
void gemm_k(const float* __restrict__ Ain, const float* __restrict__ Bw,
            float* __restrict__ Cout, int Kdim, int Ndim)
{
    const float* A = (MODE == 1) ? g_Y : Ain;

    const int m0 = blockIdx.y * 128;
    const int n0 = blockIdx.x * 64;

    __shared__ __align__(16) float As[16][132];   // [k][m], padded
    __shared__ __align__(16) float Bs[16][64];    // [k][n]

    const int tid = threadIdx.x;
    const int tx  = tid & 15;   // column group: cols tx*4 .. tx*4+3
    const int ty  = tid >> 4;   // row group:    rows ty*8 .. ty*8+7

    float acc[8][4];
#pragma unroll
    for (int i = 0; i < 8; i++)
#pragma unroll
        for (int j = 0; j < 4; j++) acc[i][j] = 0.0f;

    for (int k0 = 0; k0 < Kdim; k0 += 16) {
        // Load A tile 128x16 (transposed into As[k][m])
#pragma unroll
        for (int i = 0; i < 8; i++) {
            int idx = tid + i * 256;          // 0..2047
            int m   = idx >> 4;
            int kk  = idx & 15;
            As[kk][m] = A[(m0 + m) * Kdim + k0 + kk];
        }
        // Load B tile 16x64
#pragma unroll
        for (int i = 0; i < 4; i++) {
            int idx = tid + i * 256;          // 0..1023
            int kk  = idx >> 6;
            int n   = idx & 63;
            Bs[kk][n] = Bw[(k0 + kk) * Ndim + n0 + n];
        }
        __syncthreads();

#pragma unroll
        for (int kk = 0; kk < 16; kk++) {
            float4 a0 = *(const float4*)&As[kk][ty * 8];
            float4 a1 = *(const float4*)&As[kk][ty * 8 + 4];
            float4 b0 = *(const float4*)&Bs[kk][tx * 4];
            float a[8] = {a0.x, a0.y, a0.z, a0.w, a1.x, a1.y, a1.z, a1.w};
            float b[4] = {b0.x, b0.y, b0.z, b0.w};
#pragma unroll
            for (int i = 0; i < 8; i++)
#pragma unroll
                for (int j = 0; j < 4; j++)
                    acc[i][j] += a[i] * b[j];
        }
        __syncthreads();
    }

    if (MODE == 0) {
        // Whole 64-col block maps to a single (part, head): n0 % 64 == 0, D == 64
        int part = n0 >> 10;            // 0=q, 1=k, 2=v
        int h    = (n0 & 1023) >> 6;
        float* dst  = (part == 0) ? g_Q : (part == 1) ? g_K : g_V;
        float scale = (part == 0) ? 0.125f : 1.0f;   // 1/sqrt(64) folded into Q
#pragma unroll
        for (int i = 0; i < 8; i++) {
            int m = m0 + ty * 8 + i;
            int b = m >> 11;            // / TT
            int t = m & (TT - 1);
            int base = ((b * NH + h) * TT + t) * HD;
            float4 v = make_float4(acc[i][0] * scale, acc[i][1] * scale,
                                   acc[i][2] * scale, acc[i][3] * scale);
            *(float4*)(dst + base + tx * 4) = v;
        }
    } else {
#pragma unroll
        for (int i = 0; i < 8; i++) {
            int m = m0 + ty * 8 + i;
            float4 v = make_float4(acc[i][0], acc[i][1], acc[i][2], acc[i][3]);
            *(float4*)(Cout + m * Ndim + n0 + tx * 4) = v;
        }
    }
}

// ---------------------------------------------------------------------------
// Sliding-window flash attention. One CTA = (b,h) x 128 queries; one thread
// owns one query row (q vector + fp32 accumulator in registers). K/V staged
// in SMEM 32 keys at a time (reads are warp-broadcast). Online softmax in
// chunks of 16 keys to bound register pressure.
// ---------------------------------------------------------------------------
__global__ __launch_bounds__(128)
void attn_k()
{
    const int bh  = blockIdx.y;               // 0..B*H-1
    const int q0  = blockIdx.x * 128;
    const int tid = threadIdx.x;
    const int q   = q0 + tid;

    const float* Qb = g_Q + bh * (TT * HD);
    const float* Kb = g_K + bh * (TT * HD);
    const float* Vb = g_V + bh * (TT * HD);

    __shared__ __align__(16) float Ks[32][64];
    __shared__ __align__(16) float Vs[32][64];

    float qreg[64];
#pragma unroll
    for (int d4 = 0; d4 < 16; d4++) {
        float4 v = ((const float4*)(Qb + q * HD))[d4];
        qreg[d4 * 4 + 0] = v.x; qreg[d4 * 4 + 1] = v.y;
        qreg[d4 * 4 + 2] = v.z; qreg[d4 * 4 + 3] = v.w;
    }

    float acc[64];
#pragma unroll
    for (int d = 0; d < 64; d++) acc[d] = 0.0f;
    float mval = -1e30f;
    float lval = 0.0f;

    int lo  = q0 - (WIN - 1);
    if (lo < 0) lo = 0;
    int kb0  = lo & ~31;
    int kend = q0 + 128;

    for (int kb = kb0; kb < kend; kb += 32) {
        // Stage 32 keys + values (coalesced float4 loads)
#pragma unroll
        for (int i = 0; i < 4; i++) {
            int idx = tid + i * 128;        // 0..511 (float4 units)
            int r   = idx >> 4;
            int dq  = idx & 15;
            ((float4*)Ks[r])[dq] = ((const float4*)(Kb + (kb + r) * HD))[dq];
            ((float4*)Vs[r])[dq] = ((const float4*)(Vb + (kb + r) * HD))[dq];
        }
        __syncthreads();

#pragma unroll
        for (int half = 0; half < 2; half++) {
            const int jb = half * 16;
            float p[16];
            float bmax = -1e30f;

            // QK^T for 16 keys
#pragma unroll
            for (int j = 0; j < 16; j++) {
                const float4* kp = (const float4*)Ks[jb + j];
                float s0 = 0.f, s1 = 0.f, s2 = 0.f, s3 = 0.f;
#pragma unroll
                for (int d4 = 0; d4 < 16; d4++) {
                    float4 kk = kp[d4];
                    s0 += qreg[d4 * 4 + 0] * kk.x;
                    s1 += qreg[d4 * 4 + 1] * kk.y;
                    s2 += qreg[d4 * 4 + 2] * kk.z;
                    s3 += qreg[d4 * 4 + 3] * kk.w;
                }
                float s  = (s0 + s1) + (s2 + s3);
                int   jg = kb + jb + j;
                bool  valid = (jg <= q) && (jg > q - WIN);
                s = valid ? s : -1e30f;
                p[j] = s;
                bmax = fmaxf(bmax, s);
            }

            float mnew  = fmaxf(mval, bmax);
            float alpha = __expf(mval - mnew);  // 1.0 when both still -1e30
            float psum  = 0.0f;
#pragma unroll
            for (int j = 0; j < 16; j++) {
                int  jg    = kb + jb + j;
                bool valid = (jg <= q) && (jg > q - WIN);
                float e = valid ? __expf(p[j] - mnew) : 0.0f;
                p[j] = e;
                psum += e;
            }
            lval = lval * alpha + psum;
            mval = mnew;

#pragma unroll
            for (int d = 0; d < 64; d++) acc[d] *= alpha;

            // acc += P @ V
#pragma unroll
            for (int j = 0; j < 16; j++) {
                float pj = p[j];
                const float4* vp = (const float4*)Vs[jb + j];
#pragma unroll
                for (int d4 = 0; d4 < 16; d4++) {
                    float4 vv = vp[d4];
                    acc[d4 * 4 + 0] += pj * vv.x;
                    acc[d4 * 4 + 1] += pj * vv.y;
                    acc[d4 * 4 + 2] += pj * vv.z;
                    acc[d4 * 4 + 3] += pj * vv.w;
                }
            }
        }
        __syncthreads();
    }

    // Write back to [B, T, C] layout for the projection GEMM
    float inv = 1.0f / lval;
    int b = bh >> 4;
    int h = bh & 15;
    float* yp = g_Y + (b * TT + q) * CC + h * HD;
#pragma unroll
    for (int d4 = 0; d4 < 16; d4++) {
        float4 o = make_float4(acc[d4 * 4 + 0] * inv, acc[d4 * 4 + 1] * inv,
                               acc[d4 * 4 + 2] * inv, acc[d4 * 4 + 3] * inv);
        ((float4*)yp)[d4] = o;
    }
}

// ---------------------------------------------------------------------------
// Launch: 3 kernels on the capture stream. No sync, no allocation.
// ---------------------------------------------------------------------------
extern "C" void kernel_launch(void* const* d_in, const int* in_sizes, int n_in,
                              void* d_out, int out_size)
{
    const float* x      = (const float*)d_in[0];   // [2, 2048, 1024]
    const float* w_attn = (const float*)d_in[1];   // [1024, 3072]
    const float* w_proj = (const float*)d_in[2];   // [1024, 1024]
    float* out = (float*)d_out;                    // [2, 2048, 1024]

    dim3 g1(NQKV / 64, MTOT / 128);                // (48, 32)
    gemm_k<0><<<g1, 256>>>(x, w_attn, nullptr, CC, NQKV);

    dim3 ga(TT / 128, NB * NH);                    // (16, 32)
    attn_k<<<ga, 128>>>();

    dim3 g2(CC / 64, MTOT / 128);                  // (16, 32)
    gemm_k<1><<<g2, 256>>>(nullptr, w_proj, out, CC, CC);
}